// round 17
// baseline (speedup 1.0000x reference)
#include <cuda_runtime.h>
#include <cstdint>

#define NAG   4096
#define TOPK  12
#define NSEL  13                 // extract 13, fix up ordering with real sqrt
#define NITEMS (NAG * TOPK)      // 49152
#define T1    256
#define EPT   16                 // elements per thread = 4096/256
#define CCAP  256                // per-row candidate capacity
#define ROWS  2                  // agent rows per block
#define NIT   24                 // items per block = ROWS*TOPK
#define ISTR  26                 // item stride (floats), even -> u64 aligned
#define DSM_FLOATS ((64 + 128) * ISTR)
#define DSM_BYTES  (DSM_FLOATS * 4)      // 19,968 B

#define U64MAX 0xFFFFFFFFFFFFFFFFULL
typedef unsigned long long u64;

__device__ float g_W2t[64 * 128];        // [k][m]
__device__ float g_W3t[128 * 64];        // [k][o]

static __device__ __forceinline__ u64 u64min(u64 a, u64 b) { return (b < a) ? b : a; }

// ---- packed f32x2 helpers (bitwise identical to two scalar fmaf's) --------
static __device__ __forceinline__ u64 pk2(float lo, float hi) {
    u64 r;
    asm("mov.b64 %0, {%1, %2};" : "=l"(r) : "f"(lo), "f"(hi));
    return r;
}
static __device__ __forceinline__ u64 fma2(u64 a, u64 b, u64 c) {
    u64 d;
    asm("fma.rn.f32x2 %0, %1, %2, %3;" : "=l"(d) : "l"(a), "l"(b), "l"(c));
    return d;
}
static __device__ __forceinline__ float2 up2(u64 v) {
    float2 f;
    asm("mov.b64 {%0, %1}, %2;" : "=f"(f.x), "=f"(f.y) : "l"(v));
    return f;
}

// ---------------------------------------------------------------------------
// Kernel T: transpose W2 -> g_W2t [k][m], W3 -> g_W3t [k][o].
// ---------------------------------------------------------------------------
__global__ void __launch_bounds__(T1) transpose_kernel(
    const float* __restrict__ W2, const float* __restrict__ W3)
{
    const int g = blockIdx.x * T1 + threadIdx.x;
    const int stride = gridDim.x * T1;
    for (int s = g; s < 128 * 64; s += stride) {
        const int m = s >> 6, k = s & 63;
        g_W2t[k * 128 + m] = W2[s];
    }
    for (int s = g; s < 64 * 128; s += stride) {
        const int o = s >> 7, m = s & 127;
        g_W3t[m * 64 + o] = W3[s];
    }
}

// ---------------------------------------------------------------------------
// Fused kernel: block = 2 agent rows (fine granularity -> 3.5 waves so
// streaming blocks and MLP blocks co-reside chip-wide).
//  Phase 1 (x2, proven): stream row, threshold filter (max of 16 half-warp
//    minima => >=16 candidates), per-row smem candidate buffer.
//  Phase 1b: warps 0..1 extract their row in parallel (13 exact extract-min
//    passes + monotone-sqrt re-key fixup; overflow -> deterministic rescan).
//  Phase 2: 24-item MLP:
//    layer1 thread=(o, 6-item group); layer2 thread=2m x 6i (3 f32x2 pairs);
//    layer3 thread=1o x 6i K=128; fused layer4 partials -> 64-way sum.
// ---------------------------------------------------------------------------
__global__ void __launch_bounds__(T1) fused_all_kernel(
    const float* __restrict__ x,  const float* __restrict__ rp,
    const float* __restrict__ W1, const float* __restrict__ b1,
    const float* __restrict__ b2, const float* __restrict__ b3,
    const float* __restrict__ W4, const float* __restrict__ b4,
    float* __restrict__ out)
{
    extern __shared__ float dsm[];
    float* H1s = dsm;                    // [64][ISTR]
    float* H2s = dsm + 64 * ISTR;        // [128][ISTR]
    u64*   scand = reinterpret_cast<u64*>(H2s);   // [ROWS*CCAP], dead by stage B
    float* red = H1s;                    // layer4 partials alias H1s

    __shared__ float    feats[NIT * 8];
    __shared__ float    W1s[64 * 6];
    __shared__ float    b1s[64];
    __shared__ float    masks[NIT];
    __shared__ int      sidx[NIT];
    __shared__ unsigned tmin16[16];
    __shared__ unsigned sthresh;
    __shared__ int      scnt2[ROWS];

    const int tid  = threadIdx.x;
    const int w    = tid >> 5;
    const int lane = tid & 31;
    const int i2   = blockIdx.x * ROWS;

    for (int s = tid; s < 384; s += T1) W1s[s] = W1[s];
    if (tid < 64) b1s[tid] = b1[tid];
    if (tid < ROWS) scnt2[tid] = 0;

    // ---------------- phase 1: per-row streaming filter x2 -----------------
#pragma unroll 1
    for (int r = 0; r < ROWS; ++r) {
        const float* row = x + (size_t)(i2 + r) * (NAG * 4);
        unsigned sb[EPT];
#pragma unroll
        for (int t = 0; t < EPT; ++t) {
            const int j = tid + t * T1;
            const float2 v = __ldcs(reinterpret_cast<const float2*>(row + (size_t)j * 4));
            const float s = __fadd_rn(__fadd_rn(__fmul_rn(v.x, v.x), 1e-6f),
                                      __fadd_rn(__fmul_rn(v.y, v.y), 1e-6f));
            sb[t] = __float_as_uint(s);
        }

        unsigned mymin = sb[0];
#pragma unroll
        for (int t = 1; t < EPT; ++t) mymin = (sb[t] < mymin) ? sb[t] : mymin;

        unsigned h = mymin;
#pragma unroll
        for (int off = 1; off <= 8; off <<= 1) {
            const unsigned o = __shfl_xor_sync(0xffffffffu, h, off);
            h = (o < h) ? o : h;
        }
        if ((lane & 15) == 0) tmin16[w * 2 + (lane >> 4)] = h;
        __syncthreads();

        if (w == 0 && lane < 16) {
            const unsigned mx = __reduce_max_sync(0xFFFFu, tmin16[lane]);
            if (lane == 0) sthresh = mx;
        }
        __syncthreads();

        const unsigned thr = sthresh;
        u64* cand = scand + r * CCAP;
#pragma unroll
        for (int t = 0; t < EPT; ++t) {
            if (sb[t] <= thr) {
                const int pos = atomicAdd(&scnt2[r], 1);
                if (pos < CCAP)
                    cand[pos] = ((u64)sb[t] << 32) | (unsigned)(tid + t * T1);
            }
        }
        __syncthreads();
    }

    // ---------------- phase 1b: warps 0..1 extract their row ---------------
    if (w < ROWS) {
        const int n = scnt2[w];
        const u64* cand = scand + w * CCAP;
        u64 fk[NSEL];
        u64 prev = 0;

        if (n <= CCAP) {
            u64 ck[CCAP / 32];
#pragma unroll
            for (int t = 0; t < CCAP / 32; ++t) {
                const int idx = lane + t * 32;
                ck[t] = (idx < n) ? cand[idx] : U64MAX;
            }
#pragma unroll 1
            for (int pass = 0; pass < NSEL; ++pass) {
                u64 lmin = U64MAX;
#pragma unroll
                for (int t = 0; t < CCAP / 32; ++t)
                    if (ck[t] > prev) lmin = u64min(lmin, ck[t]);
                u64 v = lmin;
#pragma unroll
                for (int off = 16; off > 0; off >>= 1) {
                    const u64 o = __shfl_xor_sync(0xffffffffu, v, off);
                    v = u64min(v, o);
                }
                fk[pass] = v;
                prev = v;
            }
        } else {
            // overflow fallback: deterministic full-row rescan (rare/never)
            const float* row = x + (size_t)(i2 + w) * (NAG * 4);
#pragma unroll 1
            for (int pass = 0; pass < NSEL; ++pass) {
                u64 lmin = U64MAX;
                for (int t = 0; t < NAG / 32; ++t) {
                    const int j = lane + t * 32;
                    const float2 v2 = *reinterpret_cast<const float2*>(row + (size_t)j * 4);
                    const float s = __fadd_rn(__fadd_rn(__fmul_rn(v2.x, v2.x), 1e-6f),
                                              __fadd_rn(__fmul_rn(v2.y, v2.y), 1e-6f));
                    const u64 k = ((u64)__float_as_uint(s) << 32) | (unsigned)j;
                    if (k > prev) lmin = u64min(lmin, k);
                }
                u64 v = lmin;
#pragma unroll
                for (int off = 16; off > 0; off >>= 1) {
                    const u64 o = __shfl_xor_sync(0xffffffffu, v, off);
                    v = u64min(v, o);
                }
                fk[pass] = v;
                prev = v;
            }
        }

        if (lane == 0) {
#pragma unroll
            for (int t = 0; t < NSEL; ++t) {
                const u64 k = fk[t];
                const float s  = __uint_as_float((unsigned)(k >> 32));
                const float dn = __fsqrt_rn(s);
                fk[t] = ((u64)__float_as_uint(dn) << 32) | (k & 0xFFFFFFFFULL);
            }
#pragma unroll
            for (int a = 1; a < NSEL; ++a) {
                const u64 key = fk[a];
                int b = a - 1;
#pragma unroll
                for (int q = 0; q < NSEL - 1; ++q) {
                    if (b >= 0 && fk[b] > key) { fk[b + 1] = fk[b]; b--; }
                }
                fk[b + 1] = key;
            }
#pragma unroll
            for (int t = 0; t < TOPK; ++t)
                sidx[w * TOPK + t] = (int)(unsigned)(fk[t] & 0xFFFFFFFFULL);
        }
    }
    __syncthreads();

    // ---------------- phase 2a: features + mask/index outputs --------------
    if (tid < NIT) {
        const int i = i2 + tid / TOPK;
        const int j = sidx[tid];
        const float4 v = *reinterpret_cast<const float4*>(
            x + ((size_t)i * NAG + (size_t)j) * 4);
        const float s2 = __fadd_rn(__fadd_rn(__fmul_rn(v.x, v.x), 1e-4f),
                                   __fadd_rn(__fmul_rn(v.y, v.y), 1e-4f));
        const float dn = __fsqrt_rn(s2);
        const float r  = rp[0];
        const float mk = (dn <= 1.0f) ? 1.0f : 0.0f;
        float* f = feats + tid * 8;
        f[0] = v.x; f[1] = v.y; f[2] = v.z; f[3] = v.w;
        f[4] = (i == j) ? 1.0f : 0.0f;
        f[5] = dn - r;
        masks[tid] = mk;
        const int item = i2 * TOPK + tid;
        out[NITEMS + item] = mk;
        out[2 * NITEMS + 2 * item + 0] = (float)i;
        out[2 * NITEMS + 2 * item + 1] = (float)j;
    }
    __syncthreads();

    // ---------------- phase 2b: layer1 (6 -> 64) -> H1s[o][it] -------------
    {
        const int o  = tid & 63;
        const int g  = tid >> 6;             // 4 groups x 6 items
        const float* wp = W1s + o * 6;
        const float w0 = wp[0], w1 = wp[1], w2 = wp[2];
        const float w3 = wp[3], w4v = wp[4], w5 = wp[5];
        const float bb = b1s[o];
#pragma unroll
        for (int e = 0; e < 6; ++e) {
            const int it = g * 6 + e;
            const float* f = feats + it * 8;
            float a = bb;
            a = fmaf(w0, f[0], a); a = fmaf(w1, f[1], a); a = fmaf(w2, f[2], a);
            a = fmaf(w3, f[3], a); a = fmaf(w4v, f[4], a); a = fmaf(w5, f[5], a);
            H1s[o * ISTR + it] = fmaxf(a, 0.0f);
        }
    }
    __syncthreads();

    // ------- phase 2c: layer2 GEMM (K=64), thread = 2m x 6i, f32x2 ---------
    {
        const int m0 = (tid >> 2) * 2;       // 0..126
        const int i0 = (tid & 3) * 6;        // 0..18 (3 pairs)

        u64 acc[2][3];
#pragma unroll
        for (int mm = 0; mm < 2; ++mm) {
            const float b = b2[m0 + mm];
            const u64 pb = pk2(b, b);
            acc[mm][0] = pb; acc[mm][1] = pb; acc[mm][2] = pb;
        }

#pragma unroll 4
        for (int k = 0; k < 64; ++k) {
            const float2 a = *reinterpret_cast<const float2*>(g_W2t + k * 128 + m0);
            const float* hrow = H1s + k * ISTR + i0;
            const u64 d0 = *reinterpret_cast<const u64*>(hrow);
            const u64 d1 = *reinterpret_cast<const u64*>(hrow + 2);
            const u64 d2 = *reinterpret_cast<const u64*>(hrow + 4);
            const u64 ax = pk2(a.x, a.x);
            const u64 ay = pk2(a.y, a.y);
            acc[0][0] = fma2(ax, d0, acc[0][0]); acc[0][1] = fma2(ax, d1, acc[0][1]);
            acc[0][2] = fma2(ax, d2, acc[0][2]);
            acc[1][0] = fma2(ay, d0, acc[1][0]); acc[1][1] = fma2(ay, d1, acc[1][1]);
            acc[1][2] = fma2(ay, d2, acc[1][2]);
        }
        __syncthreads();                     // scand (aliasing H2s) fully dead

#pragma unroll
        for (int mm = 0; mm < 2; ++mm) {
            float* dst = H2s + (m0 + mm) * ISTR + i0;
            const float2 p0 = up2(acc[mm][0]);
            const float2 p1 = up2(acc[mm][1]);
            const float2 p2 = up2(acc[mm][2]);
            float2 s0, s1, s2;
            s0.x = fmaxf(p0.x, 0.f); s0.y = fmaxf(p0.y, 0.f);
            s1.x = fmaxf(p1.x, 0.f); s1.y = fmaxf(p1.y, 0.f);
            s2.x = fmaxf(p2.x, 0.f); s2.y = fmaxf(p2.y, 0.f);
            *reinterpret_cast<float2*>(dst)     = s0;
            *reinterpret_cast<float2*>(dst + 2) = s1;
            *reinterpret_cast<float2*>(dst + 4) = s2;
        }
    }
    __syncthreads();

    // ------- phase 2d: layer3 GEMM (K=128), thread = 1o x 6i + layer4 ------
    {
        const int o  = tid & 63;
        const int ig = (tid >> 6) * 6;       // items ig..ig+5

        u64 acc[3];
        {
            const float b = b3[o];
            const u64 pb = pk2(b, b);
            acc[0] = pb; acc[1] = pb; acc[2] = pb;
        }

#pragma unroll 4
        for (int k = 0; k < 128; ++k) {
            const float wv = g_W3t[k * 64 + o];
            const u64 wd = pk2(wv, wv);
            const float* hrow = H2s + k * ISTR + ig;
            const u64 d0 = *reinterpret_cast<const u64*>(hrow);
            const u64 d1 = *reinterpret_cast<const u64*>(hrow + 2);
            const u64 d2 = *reinterpret_cast<const u64*>(hrow + 4);
            acc[0] = fma2(wd, d0, acc[0]);
            acc[1] = fma2(wd, d1, acc[1]);
            acc[2] = fma2(wd, d2, acc[2]);
        }

        // relu + layer4 partial for this thread's single o
        const float wo = W4[o];
        const float2 q0 = up2(acc[0]);
        const float2 q1 = up2(acc[1]);
        const float2 q2 = up2(acc[2]);
        float p[6];
        p[0] = wo * fmaxf(q0.x, 0.f); p[1] = wo * fmaxf(q0.y, 0.f);
        p[2] = wo * fmaxf(q1.x, 0.f); p[3] = wo * fmaxf(q1.y, 0.f);
        p[4] = wo * fmaxf(q2.x, 0.f); p[5] = wo * fmaxf(q2.y, 0.f);
        __syncthreads();                     // H1s (stage B input) fully dead
        float* rd = red + o * ISTR + ig;     // red aliases H1s
        rd[0] = p[0]; rd[1] = p[1]; rd[2] = p[2];
        rd[3] = p[3]; rd[4] = p[4]; rd[5] = p[5];
    }
    __syncthreads();

    // ---------------- phase 2e: final 64-way sum per item ------------------
    if (tid < NIT) {
        float s = 0.f;
#pragma unroll
        for (int o = 0; o < 64; ++o) s += red[o * ISTR + tid];
        out[i2 * TOPK + tid] = (s + b4[0]) * masks[tid];
    }
}

extern "C" void kernel_launch(void* const* d_in, const int* in_sizes, int n_in,
                              void* d_out, int out_size) {
    const float* x  = (const float*)d_in[0];
    const float* r  = (const float*)d_in[1];
    const float* W1 = (const float*)d_in[2];
    const float* b1 = (const float*)d_in[3];
    const float* W2 = (const float*)d_in[4];
    const float* b2 = (const float*)d_in[5];
    const float* W3 = (const float*)d_in[6];
    const float* b3 = (const float*)d_in[7];
    const float* W4 = (const float*)d_in[8];
    const float* b4 = (const float*)d_in[9];
    float* out = (float*)d_out;

    transpose_kernel<<<32, T1>>>(W2, W3);
    fused_all_kernel<<<NAG / ROWS, T1, DSM_BYTES>>>(
        x, r, W1, b1, b2, b3, W4, b4, out);
}